// round 14
// baseline (speedup 1.0000x reference)
#include <cuda_runtime.h>
#include <stdint.h>

// Problem constants (from reference)
#define GX 352
#define GY 400
#define GZ 1
#define NB 4
#define NSEG (NB * GZ * GY * GX)    // 563200
#define NC 4
#define NP 2000000

// Output layout: [mean: NSEG*NC floats][counts: NSEG floats]
#define OUT_TOTAL (NSEG * (NC + 1)) // 2816000 floats

// Persistent-grid size: 148 SMs x 8 resident CTAs @ 256 threads
#define SCATTER_BLOCKS 1184
#define SCATTER_THREADS 256

// ---------------------------------------------------------------------------
// Persistent scratch accumulator. Zero-initialized at module load; the divide
// kernel restores the all-zeros invariant after consuming it, so every graph
// replay starts from zeros -> deterministic, and NO memset pass is needed.
//   [0 .. NSEG*4)          per-segment feature sums (float4 per seg)
//   [NSEG*4 .. NSEG*5)     per-segment counts
// ---------------------------------------------------------------------------
__device__ float g_scratch[NSEG * (NC + 1)];

__device__ __forceinline__ void red_add_v4(float* dst, float4 f) {
    asm volatile("red.global.add.v4.f32 [%0], {%1, %2, %3, %4};"
                 :: "l"(dst), "f"(f.x), "f"(f.y), "f"(f.z), "f"(f.w)
                 : "memory");
}
__device__ __forceinline__ void red_add_1(float* dst) {
    asm volatile("red.global.add.f32 [%0], %1;"
                 :: "l"(dst), "f"(1.0f) : "memory");
}

// ---------------------------------------------------------------------------
// Scatter-add: persistent grid-stride (exactly-resident grid, no wave
// transitions). Each iteration handles 2 points with all 4 loads
// front-batched; ~3.3 unrolled iterations per thread.
// GZ == 1 -> seg = (b*GY + y)*GX + x.
// ---------------------------------------------------------------------------
__global__ void __launch_bounds__(SCATTER_THREADS)
scatter_add_kernel(const float4* __restrict__ features,
                   const int4*   __restrict__ coors) {
    const int stride = SCATTER_BLOCKS * SCATTER_THREADS;       // 303104
    int i = blockIdx.x * SCATTER_THREADS + threadIdx.x;

    // main loop: 2 points per iteration, strided (coalesced within warp)
    for (; i + stride < NP; i += 2 * stride) {
        int4   c0 = coors[i];
        int4   c1 = coors[i + stride];
        float4 f0 = features[i];
        float4 f1 = features[i + stride];

        int s0 = (c0.x * GY + c0.z) * GX + c0.w;
        int s1 = (c1.x * GY + c1.z) * GX + c1.w;

        red_add_v4(g_scratch + (size_t)s0 * NC, f0);
        red_add_v4(g_scratch + (size_t)s1 * NC, f1);
        red_add_1(g_scratch + NSEG * NC + s0);
        red_add_1(g_scratch + NSEG * NC + s1);
    }
    // tail: at most one more point per thread
    if (i < NP) {
        int4   c = coors[i];
        float4 f = features[i];
        int s = (c.x * GY + c.z) * GX + c.w;
        red_add_v4(g_scratch + (size_t)s * NC, f);
        red_add_1(g_scratch + NSEG * NC + s);
    }
}

// ---------------------------------------------------------------------------
// Divide + emit + scratch-restore: one segment per thread (best-measured
// config). Launched with PDL; gridDependencySynchronize gates scratch reads
// on the scatter's completed memory flush.
// ---------------------------------------------------------------------------
__global__ void __launch_bounds__(256)
divide_kernel(float* __restrict__ out) {
    int seg = blockIdx.x * blockDim.x + threadIdx.x;

    cudaGridDependencySynchronize();

    if (seg >= NSEG) return;

    float4* s_sums   = (float4*)g_scratch;
    float*  s_counts = g_scratch + NSEG * NC;

    float4 s   = s_sums[seg];
    float  cnt = s_counts[seg];

    float inv = 1.0f / fmaxf(cnt, 1.0f);
    float4 m;
    m.x = s.x * inv; m.y = s.y * inv; m.z = s.z * inv; m.w = s.w * inv;

    ((float4*)out)[seg]  = m;     // mean region
    out[NSEG * NC + seg] = cnt;   // counts region

    // restore scratch to zero for the next graph replay
    s_sums[seg]   = make_float4(0.f, 0.f, 0.f, 0.f);
    s_counts[seg] = 0.0f;
}

// ---------------------------------------------------------------------------
// Launcher: persistent scatter, then divide via programmatic dependent launch.
// ---------------------------------------------------------------------------
extern "C" void kernel_launch(void* const* d_in, const int* in_sizes, int n_in,
                              void* d_out, int out_size) {
    const float4* features = (const float4*)d_in[0];  // (NP, 4) fp32
    const int4*   coors    = (const int4*)d_in[1];    // (NP, 4) int32
    float* out = (float*)d_out;

    // 1. scatter-add (persistent grid)
    scatter_add_kernel<<<SCATTER_BLOCKS, SCATTER_THREADS>>>(features, coors);

    // 2. divide, launched programmatically-dependent on the scatter
    {
        int threads = 256;
        int blocks = (NSEG + threads - 1) / threads;

        cudaLaunchConfig_t cfg = {};
        cfg.gridDim  = dim3(blocks, 1, 1);
        cfg.blockDim = dim3(threads, 1, 1);
        cfg.dynamicSmemBytes = 0;
        cfg.stream = 0;

        cudaLaunchAttribute attrs[1];
        attrs[0].id = cudaLaunchAttributeProgrammaticStreamSerialization;
        attrs[0].val.programmaticStreamSerializationAllowed = 1;
        cfg.attrs = attrs;
        cfg.numAttrs = 1;

        cudaLaunchKernelEx(&cfg, divide_kernel, out);
    }
}

// round 15
// speedup vs baseline: 1.0021x; 1.0021x over previous
#include <cuda_runtime.h>
#include <stdint.h>

// Problem constants (from reference)
#define GX 352
#define GY 400
#define GZ 1
#define NB 4
#define NSEG (NB * GZ * GY * GX)    // 563200
#define NC 4
#define NP 2000000

// Output layout: [mean: NSEG*NC floats][counts: NSEG floats]
#define OUT_TOTAL (NSEG * (NC + 1)) // 2816000 floats

// Persistent-grid size: 148 SMs x 8 resident CTAs @ 256 threads
#define SCATTER_BLOCKS 1184
#define SCATTER_THREADS 256

// ---------------------------------------------------------------------------
// Persistent scratch accumulator. Zero-initialized at module load; the divide
// kernel restores the all-zeros invariant after consuming it, so every graph
// replay starts from zeros -> deterministic, and NO memset pass is needed.
//   [0 .. NSEG*4)          per-segment feature sums (float4 per seg)
//   [NSEG*4 .. NSEG*5)     per-segment counts
// ---------------------------------------------------------------------------
__device__ float g_scratch[NSEG * (NC + 1)];

__device__ __forceinline__ void red_add_v4(float* dst, float4 f) {
    asm volatile("red.global.add.v4.f32 [%0], {%1, %2, %3, %4};"
                 :: "l"(dst), "f"(f.x), "f"(f.y), "f"(f.z), "f"(f.w)
                 : "memory");
}
__device__ __forceinline__ void red_add_1(float* dst) {
    asm volatile("red.global.add.f32 [%0], %1;"
                 :: "l"(dst), "f"(1.0f) : "memory");
}

// ---------------------------------------------------------------------------
// Scatter-add: persistent grid-stride (exactly-resident grid, no wave
// transitions). Each iteration handles 2 points with all 4 loads
// front-batched; ~3.3 unrolled iterations per thread.
// GZ == 1 -> seg = (b*GY + y)*GX + x.
// ---------------------------------------------------------------------------
__global__ void __launch_bounds__(SCATTER_THREADS)
scatter_add_kernel(const float4* __restrict__ features,
                   const int4*   __restrict__ coors) {
    const int stride = SCATTER_BLOCKS * SCATTER_THREADS;       // 303104
    int i = blockIdx.x * SCATTER_THREADS + threadIdx.x;

    // main loop: 2 points per iteration, strided (coalesced within warp)
    for (; i + stride < NP; i += 2 * stride) {
        int4   c0 = coors[i];
        int4   c1 = coors[i + stride];
        float4 f0 = features[i];
        float4 f1 = features[i + stride];

        int s0 = (c0.x * GY + c0.z) * GX + c0.w;
        int s1 = (c1.x * GY + c1.z) * GX + c1.w;

        red_add_v4(g_scratch + (size_t)s0 * NC, f0);
        red_add_v4(g_scratch + (size_t)s1 * NC, f1);
        red_add_1(g_scratch + NSEG * NC + s0);
        red_add_1(g_scratch + NSEG * NC + s1);
    }
    // tail: at most one more point per thread
    if (i < NP) {
        int4   c = coors[i];
        float4 f = features[i];
        int s = (c.x * GY + c.z) * GX + c.w;
        red_add_v4(g_scratch + (size_t)s * NC, f);
        red_add_1(g_scratch + NSEG * NC + s);
    }
}

// ---------------------------------------------------------------------------
// Divide + emit + scratch-restore: one segment per thread (best-measured
// config). Launched with PDL; gridDependencySynchronize gates scratch reads
// on the scatter's completed memory flush.
// ---------------------------------------------------------------------------
__global__ void __launch_bounds__(256)
divide_kernel(float* __restrict__ out) {
    int seg = blockIdx.x * blockDim.x + threadIdx.x;

    cudaGridDependencySynchronize();

    if (seg >= NSEG) return;

    float4* s_sums   = (float4*)g_scratch;
    float*  s_counts = g_scratch + NSEG * NC;

    float4 s   = s_sums[seg];
    float  cnt = s_counts[seg];

    float inv = 1.0f / fmaxf(cnt, 1.0f);
    float4 m;
    m.x = s.x * inv; m.y = s.y * inv; m.z = s.z * inv; m.w = s.w * inv;

    ((float4*)out)[seg]  = m;     // mean region
    out[NSEG * NC + seg] = cnt;   // counts region

    // restore scratch to zero for the next graph replay
    s_sums[seg]   = make_float4(0.f, 0.f, 0.f, 0.f);
    s_counts[seg] = 0.0f;
}

// ---------------------------------------------------------------------------
// Launcher: persistent scatter, then divide via programmatic dependent launch.
// ---------------------------------------------------------------------------
extern "C" void kernel_launch(void* const* d_in, const int* in_sizes, int n_in,
                              void* d_out, int out_size) {
    const float4* features = (const float4*)d_in[0];  // (NP, 4) fp32
    const int4*   coors    = (const int4*)d_in[1];    // (NP, 4) int32
    float* out = (float*)d_out;

    // 1. scatter-add (persistent grid)
    scatter_add_kernel<<<SCATTER_BLOCKS, SCATTER_THREADS>>>(features, coors);

    // 2. divide, launched programmatically-dependent on the scatter
    {
        int threads = 256;
        int blocks = (NSEG + threads - 1) / threads;

        cudaLaunchConfig_t cfg = {};
        cfg.gridDim  = dim3(blocks, 1, 1);
        cfg.blockDim = dim3(threads, 1, 1);
        cfg.dynamicSmemBytes = 0;
        cfg.stream = 0;

        cudaLaunchAttribute attrs[1];
        attrs[0].id = cudaLaunchAttributeProgrammaticStreamSerialization;
        attrs[0].val.programmaticStreamSerializationAllowed = 1;
        cfg.attrs = attrs;
        cfg.numAttrs = 1;

        cudaLaunchKernelEx(&cfg, divide_kernel, out);
    }
}

// round 16
// speedup vs baseline: 1.0620x; 1.0598x over previous
#include <cuda_runtime.h>
#include <stdint.h>

// Problem constants (from reference)
#define GX 352
#define GY 400
#define GZ 1
#define NB 4
#define NSEG (NB * GZ * GY * GX)    // 563200
#define NC 4
#define NP 2000000

// Output layout: [mean: NSEG*NC floats][counts: NSEG floats]
#define OUT_TOTAL (NSEG * (NC + 1)) // 2816000 floats (704000 float4s)

__device__ __forceinline__ void red_add_v4(float* dst, float4 f) {
    asm volatile("red.global.add.v4.f32 [%0], {%1, %2, %3, %4};"
                 :: "l"(dst), "f"(f.x), "f"(f.y), "f"(f.z), "f"(f.w)
                 : "memory");
}
__device__ __forceinline__ void red_add_1(float* dst) {
    asm volatile("red.global.add.f32 [%0], %1;"
                 :: "l"(dst), "f"(1.0f) : "memory");
}

// ---------------------------------------------------------------------------
// Kernel 1: zero d_out (poisoned to 0xAA). Grid-stride float4 stores,
// exactly-resident grid. Runs ~2 us; hidden under the scatter's load phase
// via PDL. Also warms L2 with the accumulator region for the REDs.
// ---------------------------------------------------------------------------
#define ZERO_BLOCKS 1184
__global__ void __launch_bounds__(256)
zero_out_kernel(float4* __restrict__ out4) {
    const int n4 = OUT_TOTAL / 4;                 // 704000
    const int stride = ZERO_BLOCKS * 256;         // 303104
    const float4 z = make_float4(0.f, 0.f, 0.f, 0.f);
    for (int i = blockIdx.x * 256 + threadIdx.x; i < n4; i += stride)
        out4[i] = z;
}

// ---------------------------------------------------------------------------
// Kernel 2: scatter-add directly into d_out. One point per thread (measured
// best). Launched PDL-dependent on the zero kernel: the long-latency input
// loads are issued BEFORE gridDependencySynchronize (they don't touch d_out),
// so the zeroing overlaps the load ramp; only the REDs wait for zeros.
// GZ == 1 -> seg = (b*GY + y)*GX + x.
// ---------------------------------------------------------------------------
__global__ void __launch_bounds__(256)
scatter_add_kernel(const float4* __restrict__ features,
                   const int4*   __restrict__ coors,
                   float*        __restrict__ out) {
    int i = blockIdx.x * blockDim.x + threadIdx.x;

    int4   c = make_int4(0, 0, 0, 0);
    float4 f = make_float4(0.f, 0.f, 0.f, 0.f);
    bool active = (i < NP);
    if (active) {
        c = coors[i];                      // (b, z, y, x) — independent of d_out
        f = features[i];
    }

    // Wait for the zero kernel's stores to be visible before touching d_out.
    cudaGridDependencySynchronize();

    if (active) {
        int seg = (c.x * GY + c.z) * GX + c.w;
        red_add_v4(out + (size_t)seg * NC, f);
        red_add_1(out + (size_t)NSEG * NC + seg);
    }
}

// ---------------------------------------------------------------------------
// Kernel 3: divide in place. One segment per thread. Counts are already
// final in d_out; just scale the sums region. L2-hot reads (the REDs put the
// lines in L2). PDL-dependent on the scatter.
// ---------------------------------------------------------------------------
__global__ void __launch_bounds__(256)
divide_kernel(float* __restrict__ out) {
    int seg = blockIdx.x * blockDim.x + threadIdx.x;

    cudaGridDependencySynchronize();

    if (seg >= NSEG) return;

    float4* sums = (float4*)out;
    float4 s  = sums[seg];
    float cnt = out[(size_t)NSEG * NC + seg];

    float inv = 1.0f / fmaxf(cnt, 1.0f);
    s.x *= inv; s.y *= inv; s.z *= inv; s.w *= inv;
    sums[seg] = s;
}

// ---------------------------------------------------------------------------
// Launcher: zero -> scatter (PDL) -> divide (PDL). No scratch, no memset node.
// ---------------------------------------------------------------------------
static void launch_pdl(void* func, dim3 grid, dim3 block,
                       void** args) {
    cudaLaunchConfig_t cfg = {};
    cfg.gridDim = grid;
    cfg.blockDim = block;
    cfg.dynamicSmemBytes = 0;
    cfg.stream = 0;
    cudaLaunchAttribute attrs[1];
    attrs[0].id = cudaLaunchAttributeProgrammaticStreamSerialization;
    attrs[0].val.programmaticStreamSerializationAllowed = 1;
    cfg.attrs = attrs;
    cfg.numAttrs = 1;
    cudaLaunchKernelExC(&cfg, func, args);
}

extern "C" void kernel_launch(void* const* d_in, const int* in_sizes, int n_in,
                              void* d_out, int out_size) {
    const float4* features = (const float4*)d_in[0];  // (NP, 4) fp32
    const int4*   coors    = (const int4*)d_in[1];    // (NP, 4) int32
    float* out = (float*)d_out;

    // 1. zero d_out
    {
        float4* out4 = (float4*)d_out;
        zero_out_kernel<<<ZERO_BLOCKS, 256>>>(out4);
    }

    // 2. scatter-add (PDL on zero; loads overlap the zeroing)
    {
        int blocks = (NP + 255) / 256;
        void* args[3] = { (void*)&features, (void*)&coors, (void*)&out };
        launch_pdl((void*)scatter_add_kernel, dim3(blocks), dim3(256), args);
    }

    // 3. divide in place (PDL on scatter)
    {
        int blocks = (NSEG + 255) / 256;
        void* args[1] = { (void*)&out };
        launch_pdl((void*)divide_kernel, dim3(blocks), dim3(256), args);
    }
}